// round 10
// baseline (speedup 1.0000x reference)
#include <cuda_runtime.h>
#include <math.h>

// Problem dims (fixed by the dataset)
#define Q   512
#define D   131072           // 512*16*16
#define D4  (D/4)            // 32768 float4
#define B   2
#define A   16
#define C   19
#define HW  65536            // 256*256
#define REFINE_CONF 0.968f

// k_dots tiling: 8 rows/block, register-held tgt
#define CH     2048          // float4 per D-chunk
#define S_DOTS (D4/CH)       // 16 D-splits
#define RPB    8             // queue rows per block
#define ROWG   (Q/RPB)       // 64 row-groups
#define NDOT   (S_DOTS*ROWG) // 1024 dot blocks
#define CONFB  512           // confidence blocks: 256 pixels each (2/thread)
#define NTT    32            // tt blocks
#define NK1    (NDOT+CONFB+NTT)   // kernel-1 total blocks
// k_d2 tiling
#define S_TT   16
#define CHTT   (D4/S_TT)     // 2048 float4
#define S_D2   32
#define CH2    (D4/S_D2)     // 1024 float4
#define NK2    (32*S_D2)     // 1024 blocks

// ---------------- scratch (no allocations allowed) ----------------
__device__ float g_pqq[S_DOTS][Q];        // partial ||queue_q||^2
__device__ float g_pqt[S_DOTS][Q][B];     // partial queue_q . tgt_b
__device__ float g_ptt[S_TT][B];          // partial ||tgt_b||^2
__device__ int   g_imin[B];
__device__ float g_cd2[B];                // closest distance^2
__device__ float g_pd2[S_D2][B][A];       // partial ||aug - closest||^2
__device__ int   g_selidx[B][16];
__device__ int   g_selcnt[B];
__device__ int   g_mcnt[B];
__device__ unsigned char g_pmask[B * HW]; // low-confidence mask
__device__ unsigned int  g_ctr1;          // last-block counters (reset in-kernel)
__device__ unsigned int  g_ctr2;

__device__ __forceinline__ float dot4(float4 a, float4 b, float acc) {
    return fmaf(a.x, b.x, fmaf(a.y, b.y, fmaf(a.z, b.z, fmaf(a.w, b.w, acc))));
}

// ---------------- kernel 1: queue dots + conf mask + tt, argmin in last block ----------------
__global__ __launch_bounds__(128) void k_dots_tt(const float* __restrict__ queue,
                                                 const float* __restrict__ tgt,
                                                 const float* __restrict__ tgt_logits) {
    const int bid = blockIdx.x;
    const int tid = threadIdx.x;
    const int lane = tid & 31, warp = tid >> 5;
    __shared__ float red[RPB * 3][128];           // 12 KB
    __shared__ int   s_last;

    if (bid < NDOT) {
        // dot blocks FIRST: saturate HBM from t=0
        const int s    = bid >> 6;                // D-split (ROWG = 64)
        const int rowg = bid & 63;
        const int q0   = rowg * RPB;
        const int i0   = s * CH;
        const float4* __restrict__ qf = (const float4*)queue;
        const float4* __restrict__ tf = (const float4*)tgt;

        float acc[RPB * 3];
#pragma unroll
        for (int v = 0; v < RPB * 3; v++) acc[v] = 0.f;

        const float4* __restrict__ qbase = qf + (size_t)q0 * D4 + i0 + tid;
        const float4* __restrict__ tbase = tf + i0 + tid;

        for (int off = 0; off < CH; off += 128) {
            float4 t0 = tbase[off];
            float4 t1 = tbase[D4 + off];
            float4 qv[RPB];
#pragma unroll
            for (int r = 0; r < RPB; r++) qv[r] = qbase[(size_t)r * D4 + off];
#pragma unroll
            for (int r = 0; r < RPB; r++) {
                acc[r * 3 + 0] = dot4(qv[r], qv[r], acc[r * 3 + 0]);
                acc[r * 3 + 1] = dot4(qv[r], t0,    acc[r * 3 + 1]);
                acc[r * 3 + 2] = dot4(qv[r], t1,    acc[r * 3 + 2]);
            }
        }

#pragma unroll
        for (int v = 0; v < RPB * 3; v++) red[v][tid] = acc[v];
        __syncthreads();
#pragma unroll
        for (int c = 0; c < 6; c++) {
            const int v = warp * 6 + c;           // 0..23
            float ssum = red[v][lane] + red[v][lane + 32] + red[v][lane + 64] + red[v][lane + 96];
#pragma unroll
            for (int o = 16; o > 0; o >>= 1) ssum += __shfl_down_sync(0xFFFFFFFFu, ssum, o);
            if (lane == 0) {
                const int r = v / 3, cc = v % 3;
                if (cc == 0) g_pqq[s][q0 + r]         = ssum;
                else         g_pqt[s][q0 + r][cc - 1] = ssum;
            }
        }
    } else if (bid < NDOT + CONFB) {
        // confidence blocks: 19 INDEPENDENT loads, then reduce. Tail filler.
        const int cb = bid - NDOT;
#pragma unroll
        for (int u = 0; u < 2; u++) {
            const int pix = cb * 256 + u * 128 + tid;
            const int b = pix >> 16;
            const int p = pix & (HW - 1);
            const float* __restrict__ tp = tgt_logits + (size_t)b * C * HW + p;
            float tl[C];
#pragma unroll
            for (int c = 0; c < C; c++) tl[c] = tp[(size_t)c * HW];
            float mx = tl[0];
#pragma unroll
            for (int c = 1; c < C; c++) mx = fmaxf(mx, tl[c]);
            float s = 0.f;
#pragma unroll
            for (int c = 0; c < C; c++) s += __expf(tl[c] - mx);
            g_pmask[pix] = ((1.0f / s) < REFINE_CONF) ? 1 : 0;
        }
    } else {
        // tt blocks: 32 of them, (sc, b)
        const int s2 = bid - NDOT - CONFB;
        const int b  = s2 & 1;
        const int sc = s2 >> 1;                   // 0..15
        const float4* __restrict__ tf = (const float4*)tgt + (size_t)b * D4 + sc * CHTT;
        float sum = 0.f;
        for (int i = tid; i < CHTT; i += 128) {
            float4 t = tf[i];
            sum = dot4(t, t, sum);
        }
#pragma unroll
        for (int o = 16; o > 0; o >>= 1) sum += __shfl_down_sync(0xFFFFFFFFu, sum, o);
        if (lane == 0) red[0][warp] = sum;
        __syncthreads();
        if (tid < 4) {
            sum = red[0][tid];
#pragma unroll
            for (int o = 2; o > 0; o >>= 1) sum += __shfl_down_sync(0xFu, sum, o);
            if (tid == 0) g_ptt[sc][b] = sum;
        }
    }

    // ---- last-block-done: argmin tail (threadfence-reduction pattern) ----
    __syncthreads();
    if (tid == 0) {
        __threadfence();
        unsigned int old = atomicAdd(&g_ctr1, 1u);
        s_last = (old == NK1 - 1) ? 1 : 0;
    }
    __syncthreads();
    if (s_last) {
        __shared__ float tts[B];
        __shared__ float sv[128];
        __shared__ int   si[128];
        if (tid < B) {
            float t = 0.f;
#pragma unroll
            for (int s = 0; s < S_TT; s++) t += g_ptt[s][tid];
            tts[tid] = t;
        }
        __syncthreads();
        for (int b = 0; b < B; b++) {
            float bv = INFINITY; int bi = 0x7FFFFFFF;
            for (int q = tid; q < Q; q += 128) {
                float qq = 0.f, qt = 0.f;
#pragma unroll
                for (int s = 0; s < S_DOTS; s++) { qq += g_pqq[s][q]; qt += g_pqt[s][q][b]; }
                float v = qq - 2.0f * qt + tts[b];
                if (v < bv) { bv = v; bi = q; }   // q increasing => first index kept on tie
            }
            sv[tid] = bv; si[tid] = bi;
            __syncthreads();
            for (int s = 64; s > 0; s >>= 1) {
                if (tid < s) {
                    float ov = sv[tid + s]; int oi = si[tid + s];
                    if (ov < sv[tid] || (ov == sv[tid] && oi < si[tid])) { sv[tid] = ov; si[tid] = oi; }
                }
                __syncthreads();
            }
            if (tid == 0) { g_imin[b] = si[0]; g_cd2[b] = sv[0]; }
            __syncthreads();
        }
        if (tid == 0) g_ctr1 = 0;                 // reset for next graph replay
    }
}

// ---------------- kernel 2: d2 partials, selection in last block ----------------
__global__ __launch_bounds__(256) void k_d2(const float* __restrict__ auged,
                                            const float* __restrict__ queue,
                                            const int*   __restrict__ kptr) {
    const int pair = blockIdx.x & 31;            // b*A + a
    const int s    = blockIdx.x >> 5;            // 0..S_D2-1
    const int b = pair >> 4;
    const int a = pair & 15;
    const int tid = threadIdx.x;
    const int im = g_imin[b];
    const int i0 = s * CH2;                      // 1024 float4 per split
    __shared__ int s_last;

    const float4* __restrict__ af = (const float4*)(auged + ((size_t)b * A + a) * D) + i0 + tid;
    const float4* __restrict__ cf = (const float4*)(queue + (size_t)im * D) + i0 + tid;

    float4 av[4], cv[4];
#pragma unroll
    for (int u = 0; u < 4; u++) av[u] = af[u * 256];
#pragma unroll
    for (int u = 0; u < 4; u++) cv[u] = cf[u * 256];

    float sacc = 0.f;
#pragma unroll
    for (int u = 0; u < 4; u++) {
        float dx = av[u].x - cv[u].x, dy = av[u].y - cv[u].y;
        float dz = av[u].z - cv[u].z, dw = av[u].w - cv[u].w;
        sacc = fmaf(dx, dx, fmaf(dy, dy, fmaf(dz, dz, fmaf(dw, dw, sacc))));
    }
    __shared__ float red[8];
    const int lane = tid & 31, warp = tid >> 5;
#pragma unroll
    for (int o = 16; o > 0; o >>= 1) sacc += __shfl_down_sync(0xFFFFFFFFu, sacc, o);
    if (lane == 0) red[warp] = sacc;
    __syncthreads();
    if (tid < 8) {
        sacc = red[tid];
#pragma unroll
        for (int o = 4; o > 0; o >>= 1) sacc += __shfl_down_sync(0xFu, sacc, o);
        if (tid == 0) g_pd2[s][b][a] = sacc;
    }

    // ---- last-block-done: selection tail ----
    __syncthreads();
    if (tid == 0) {
        __threadfence();
        unsigned int old = atomicAdd(&g_ctr2, 1u);
        s_last = (old == NK2 - 1) ? 1 : 0;
    }
    __syncthreads();
    if (s_last) {
        __shared__ float d2s[B][A];
        {   // 8 threads per (b,a) pair, 4 loads each + width-8 shuffle
            const int pairid = tid >> 3;          // 0..31
            const int sub    = tid & 7;
            const int bb = pairid >> 4, aa = pairid & 15;
            float v = 0.f;
#pragma unroll
            for (int ss = 0; ss < 4; ss++) v += g_pd2[sub + ss * 8][bb][aa];
#pragma unroll
            for (int o = 4; o > 0; o >>= 1) v += __shfl_down_sync(0xFFFFFFFFu, v, o, 8);
            if (sub == 0) d2s[bb][aa] = v;
        }
        __syncthreads();
        if (tid == 0) {
            int k = kptr ? kptr[0] : 5;
            if (k > 16) k = 16;
            if (k < 0)  k = 0;
            for (int bb = 0; bb < B; bb++) {
                float cd = g_cd2[bb];
                float dv[16];
                int m = 0;
#pragma unroll
                for (int aa = 0; aa < A; aa++) {
                    dv[aa] = d2s[bb][aa];
                    if (dv[aa] <= cd) m++;
                }
                bool used[16] = {false};
                int cnt = 0;
                for (int j = 0; j < k; j++) {
                    int best = -1; float bv = INFINITY;
                    for (int aa = 0; aa < A; aa++) {
                        if (!used[aa] && dv[aa] <= cd && dv[aa] < bv) { bv = dv[aa]; best = aa; }
                    }
                    if (best < 0) break;
                    used[best] = true;
                    g_selidx[bb][cnt++] = best;
                }
                g_selcnt[bb] = cnt;
                g_mcnt[bb]   = m;
            }
            g_ctr2 = 0;                           // reset for next graph replay
        }
    }
}

// ---------------- kernel 3: slim gather/argmax/gate (no preamble) ----------------
__global__ __launch_bounds__(256) void k_final(const float* __restrict__ auged_logits,
                                               const int*   __restrict__ pseudo,
                                               float* __restrict__ out) {
    const int tid = threadIdx.x;
    const int pix = blockIdx.x * 256 + tid;   // < B*HW
    const int b = pix >> 16;
    const int p = pix & (HW - 1);

    const int cnt = g_selcnt[b];              // L2-hot broadcast loads
    const int m   = g_mcnt[b];

    const int  pl    = pseudo[(size_t)b * HW + p];
    const bool pmask = g_pmask[pix] != 0;

    float acc[C];
#pragma unroll
    for (int c = 0; c < C; c++) acc[c] = 0.f;

    for (int j = 0; j < cnt; j++) {
        const int a = g_selidx[b][j];
        const float* __restrict__ lp = auged_logits + ((size_t)(b * A + a) * C) * HW + p;
        float l[C];
        float mx = -INFINITY;
#pragma unroll
        for (int c = 0; c < C; c++) { l[c] = lp[(size_t)c * HW]; mx = fmaxf(mx, l[c]); }
        float s = 0.f;
#pragma unroll
        for (int c = 0; c < C; c++) { l[c] = __expf(l[c] - mx); s += l[c]; }
        float inv = 1.0f / s;
#pragma unroll
        for (int c = 0; c < C; c++) acc[c] = fmaf(l[c], inv, acc[c]);
    }

    const float invc = 1.0f / (float)max(cnt, 1);

    int knn = 0; float bv = acc[0];
#pragma unroll
    for (int c = 1; c < C; c++) { if (acc[c] > bv) { bv = acc[c]; knn = c; } }

    int refined = (pmask && m > 0) ? knn : pl;
    out[pix] = (float)refined;

    float* __restrict__ oavg = out + (size_t)B * HW;
#pragma unroll
    for (int c = 0; c < C; c++)
        oavg[((size_t)b * C + c) * HW + p] = acc[c] * invc;
}

// ---------------- launch ----------------
extern "C" void kernel_launch(void* const* d_in, const int* in_sizes, int n_in,
                              void* d_out, int out_size) {
    const float* source_queue = (const float*)d_in[0];
    const float* tgt_feat     = (const float*)d_in[1];
    const float* tgt_logits   = (const float*)d_in[2];
    const float* auged_feat   = (const float*)d_in[3];
    const float* auged_logits = (const float*)d_in[4];
    const int*   pseudo_label = (const int*)d_in[5];
    const int*   kptr         = (n_in > 6) ? (const int*)d_in[6] : nullptr;
    float* out = (float*)d_out;

    k_dots_tt<<<NK1, 128>>>(source_queue, tgt_feat, tgt_logits);
    k_d2     <<<NK2, 256>>>(auged_feat, source_queue, kptr);
    k_final  <<<(B * HW) / 256, 256>>>(auged_logits, pseudo_label, out);
    (void)in_sizes; (void)out_size;
}

// round 11
// speedup vs baseline: 1.1274x; 1.1274x over previous
#include <cuda_runtime.h>
#include <math.h>

// Problem dims (fixed by the dataset)
#define Q   512
#define D   131072           // 512*16*16
#define D4  (D/4)            // 32768 float4
#define B   2
#define A   16
#define C   19
#define HW  65536            // 256*256
#define REFINE_CONF 0.968f

// k_dots tiling: 8 rows/block, register-held tgt
#define CH     2048          // float4 per D-chunk
#define S_DOTS (D4/CH)       // 16 D-splits
#define RPB    8             // queue rows per block
#define ROWG   (Q/RPB)       // 64 row-groups
#define NDOT   (S_DOTS*ROWG) // 1024 dot blocks
#define CONFB  512           // confidence blocks: 256 pixels each (2/thread)
#define NTT    32            // tt blocks
// k_d2 tiling
#define S_TT   16
#define CHTT   (D4/S_TT)     // 2048 float4
#define S_D2   16
#define CH2    (D4/S_D2)     // 2048 float4

// ---------------- scratch (no allocations allowed) ----------------
__device__ float g_pu[S_DOTS][Q];         // partial ||q||^2 - 2 q.t0
__device__ float g_pw[S_DOTS][Q];         // partial q.(t0 - t1)
__device__ float g_ptt[S_TT][B];          // partial ||tgt_b||^2
__device__ float g_cd2[B];                // closest distance^2 (redundantly written)
__device__ float g_pd2[S_D2][B][A];       // partial ||aug - closest||^2
__device__ unsigned char g_pmask[B * HW]; // low-confidence mask

__device__ __forceinline__ float dot4(float4 a, float4 b, float acc) {
    return fmaf(a.x, b.x, fmaf(a.y, b.y, fmaf(a.z, b.z, fmaf(a.w, b.w, acc))));
}

// ---------------- kernel 1: queue dots (u/w form) + conf mask + tt ----------------
__global__ __launch_bounds__(128) void k_dots_tt(const float* __restrict__ queue,
                                                 const float* __restrict__ tgt,
                                                 const float* __restrict__ tgt_logits) {
    const int bid = blockIdx.x;
    const int tid = threadIdx.x;
    const int lane = tid & 31, warp = tid >> 5;
    __shared__ float red[RPB * 2][128];           // 8 KB

    if (bid < NDOT) {
        const int s    = bid >> 6;                // D-split (ROWG = 64)
        const int rowg = bid & 63;
        const int q0   = rowg * RPB;
        const int i0   = s * CH;
        const float4* __restrict__ qf = (const float4*)queue;
        const float4* __restrict__ tf = (const float4*)tgt;

        float acc[RPB * 2];                       // [r*2+0]=u, [r*2+1]=w
#pragma unroll
        for (int v = 0; v < RPB * 2; v++) acc[v] = 0.f;

        const float4* __restrict__ qbase = qf + (size_t)q0 * D4 + i0 + tid;
        const float4* __restrict__ tbase = tf + i0 + tid;

        for (int off = 0; off < CH; off += 128) {
            float4 t0 = tbase[off];
            float4 t1 = tbase[D4 + off];
            float4 qv[RPB];
#pragma unroll
            for (int r = 0; r < RPB; r++) qv[r] = qbase[(size_t)r * D4 + off];
            float4 dv;                            // t0 - t1 (shared across rows)
            dv.x = t0.x - t1.x; dv.y = t0.y - t1.y;
            dv.z = t0.z - t1.z; dv.w = t0.w - t1.w;
#pragma unroll
            for (int r = 0; r < RPB; r++) {
                float4 e;                         // q - 2*t0
                e.x = fmaf(-2.f, t0.x, qv[r].x);
                e.y = fmaf(-2.f, t0.y, qv[r].y);
                e.z = fmaf(-2.f, t0.z, qv[r].z);
                e.w = fmaf(-2.f, t0.w, qv[r].w);
                acc[r * 2 + 0] = dot4(qv[r], e,  acc[r * 2 + 0]);
                acc[r * 2 + 1] = dot4(qv[r], dv, acc[r * 2 + 1]);
            }
        }

#pragma unroll
        for (int v = 0; v < RPB * 2; v++) red[v][tid] = acc[v];
        __syncthreads();
        // 4 warps x 4 values each
#pragma unroll
        for (int c = 0; c < 4; c++) {
            const int v = warp * 4 + c;           // 0..15
            float ssum = red[v][lane] + red[v][lane + 32] + red[v][lane + 64] + red[v][lane + 96];
#pragma unroll
            for (int o = 16; o > 0; o >>= 1) ssum += __shfl_down_sync(0xFFFFFFFFu, ssum, o);
            if (lane == 0) {
                const int r = v >> 1;
                if ((v & 1) == 0) g_pu[s][q0 + r] = ssum;
                else              g_pw[s][q0 + r] = ssum;
            }
        }
    } else if (bid < NDOT + CONFB) {
        // confidence blocks: 19 INDEPENDENT loads, then reduce. Tail filler.
        const int cb = bid - NDOT;
#pragma unroll
        for (int u = 0; u < 2; u++) {
            const int pix = cb * 256 + u * 128 + tid;
            const int b = pix >> 16;
            const int p = pix & (HW - 1);
            const float* __restrict__ tp = tgt_logits + (size_t)b * C * HW + p;
            float tl[C];
#pragma unroll
            for (int c = 0; c < C; c++) tl[c] = tp[(size_t)c * HW];
            float mx = tl[0];
#pragma unroll
            for (int c = 1; c < C; c++) mx = fmaxf(mx, tl[c]);
            float sum = 0.f;
#pragma unroll
            for (int c = 0; c < C; c++) sum += __expf(tl[c] - mx);
            g_pmask[pix] = ((1.0f / sum) < REFINE_CONF) ? 1 : 0;
        }
    } else {
        // tt blocks: 32 of them, (sc, b)
        const int s2 = bid - NDOT - CONFB;
        const int b  = s2 & 1;
        const int sc = s2 >> 1;                   // 0..15
        const float4* __restrict__ tf = (const float4*)tgt + (size_t)b * D4 + sc * CHTT;
        float sum = 0.f;
        for (int i = tid; i < CHTT; i += 128) {
            float4 t = tf[i];
            sum = dot4(t, t, sum);
        }
#pragma unroll
        for (int o = 16; o > 0; o >>= 1) sum += __shfl_down_sync(0xFFFFFFFFu, sum, o);
        if (lane == 0) red[0][warp] = sum;
        __syncthreads();
        if (tid < 4) {
            sum = red[0][tid];
#pragma unroll
            for (int o = 2; o > 0; o >>= 1) sum += __shfl_down_sync(0xFu, sum, o);
            if (tid == 0) g_ptt[sc][b] = sum;
        }
    }
}

// ---------------- kernel 2: per-block argmin preamble + d2 partials ----------------
__global__ __launch_bounds__(256) void k_d2(const float* __restrict__ auged,
                                            const float* __restrict__ queue) {
    const int pair = blockIdx.x & 31;            // b*A + a
    const int s    = blockIdx.x >> 5;            // 0..S_D2-1
    const int b = pair >> 4;
    const int a = pair & 15;
    const int tid = threadIdx.x;
    const int lane = tid & 31, warp = tid >> 5;

    __shared__ float tts[B];
    __shared__ float sv[256];
    __shared__ int   si[256];
    __shared__ int   s_imin[B];

    // ---- preamble: recompute argmin from L2-hot partials (no cross-block sync) ----
    if (tid < B) {
        float t = 0.f;
#pragma unroll
        for (int ss = 0; ss < S_TT; ss++) t += g_ptt[ss][tid];
        tts[tid] = t;
    }
    // per-thread sums for q = tid and q + 256
    float u1 = 0.f, w1 = 0.f, u2 = 0.f, w2 = 0.f;
#pragma unroll
    for (int ss = 0; ss < S_DOTS; ss++) {
        u1 += g_pu[ss][tid];
        w1 += g_pw[ss][tid];
        u2 += g_pu[ss][tid + 256];
        w2 += g_pw[ss][tid + 256];
    }
    __syncthreads();
#pragma unroll
    for (int bb = 0; bb < B; bb++) {
        float v1, v2;
        if (bb == 0) { v1 = u1 + tts[0];               v2 = u2 + tts[0]; }
        else         { v1 = fmaf(2.f, w1, u1) + tts[1]; v2 = fmaf(2.f, w2, u2) + tts[1]; }
        float bv; int bi;
        if (v2 < v1) { bv = v2; bi = tid + 256; } else { bv = v1; bi = tid; }
        sv[tid] = bv; si[tid] = bi;
        __syncthreads();
        for (int st = 128; st > 0; st >>= 1) {
            if (tid < st) {
                float ov = sv[tid + st]; int oi = si[tid + st];
                if (ov < sv[tid] || (ov == sv[tid] && oi < si[tid])) { sv[tid] = ov; si[tid] = oi; }
            }
            __syncthreads();
        }
        if (tid == 0) {
            s_imin[bb] = si[0];
            g_cd2[bb]  = sv[0];   // identical value from every block: benign race
        }
        __syncthreads();
    }

    // ---- main: ||aug[b,a] - closest_b||^2 over this block's D-chunk ----
    const int im = s_imin[b];
    const int i0 = s * CH2;                      // 2048 float4 per split
    const float4* __restrict__ af = (const float4*)(auged + ((size_t)b * A + a) * D) + i0 + tid;
    const float4* __restrict__ cf = (const float4*)(queue + (size_t)im * D) + i0 + tid;

    float sacc = 0.f;
#pragma unroll
    for (int it = 0; it < 2; it++) {
        const int off = it * 1024;
        float4 av[4], cv[4];
#pragma unroll
        for (int u = 0; u < 4; u++) av[u] = af[off + u * 256];
#pragma unroll
        for (int u = 0; u < 4; u++) cv[u] = cf[off + u * 256];
#pragma unroll
        for (int u = 0; u < 4; u++) {
            float dx = av[u].x - cv[u].x, dy = av[u].y - cv[u].y;
            float dz = av[u].z - cv[u].z, dw = av[u].w - cv[u].w;
            sacc = fmaf(dx, dx, fmaf(dy, dy, fmaf(dz, dz, fmaf(dw, dw, sacc))));
        }
    }
#pragma unroll
    for (int o = 16; o > 0; o >>= 1) sacc += __shfl_down_sync(0xFFFFFFFFu, sacc, o);
    if (lane == 0) sv[warp] = sacc;
    __syncthreads();
    if (tid < 8) {
        sacc = sv[tid];
#pragma unroll
        for (int o = 4; o > 0; o >>= 1) sacc += __shfl_down_sync(0xFFu, sacc, o);
        if (tid == 0) g_pd2[s][b][a] = sacc;
    }
}

// ---------------- kernel 3: parallel select preamble + gather/argmax/gate ----------------
__global__ __launch_bounds__(256) void k_final(const float* __restrict__ auged_logits,
                                               const int*   __restrict__ pseudo,
                                               const int*   __restrict__ kptr,
                                               float* __restrict__ out) {
    __shared__ float d2s[B][A];
    __shared__ int   ssel[B][16];
    __shared__ int   scnt[B];
    __shared__ int   smc[B];
    const int tid = threadIdx.x;

    const int pix = blockIdx.x * 256 + tid;   // < B*HW
    const int b = pix >> 16;
    const int p = pix & (HW - 1);

    // issue independent loads before the preamble barriers
    const int  pl    = pseudo[(size_t)b * HW + p];
    const bool pmask = g_pmask[pix] != 0;

    // parallel d2 reduce: 8 threads per (b,a) pair, 2 loads each + width-8 shuffle
    {
        const int pairid = tid >> 3;          // 0..31
        const int sub    = tid & 7;
        const int bb = pairid >> 4, aa = pairid & 15;
        float v = g_pd2[sub][bb][aa] + g_pd2[sub + 8][bb][aa];
#pragma unroll
        for (int o = 4; o > 0; o >>= 1) v += __shfl_down_sync(0xFFFFFFFFu, v, o, 8);
        if (sub == 0) d2s[bb][aa] = v;
    }
    __syncthreads();
    if (tid == 0) {
        int k = kptr ? kptr[0] : 5;
        if (k > 16) k = 16;
        if (k < 0)  k = 0;
        for (int bb = 0; bb < B; bb++) {
            float cd = g_cd2[bb];
            float dv[16];
            int m = 0;
#pragma unroll
            for (int aa = 0; aa < A; aa++) {
                dv[aa] = d2s[bb][aa];
                if (dv[aa] <= cd) m++;
            }
            bool used[16] = {false};
            int cnt = 0;
            for (int j = 0; j < k; j++) {
                int best = -1; float bv = INFINITY;
                for (int aa = 0; aa < A; aa++) {
                    if (!used[aa] && dv[aa] <= cd && dv[aa] < bv) { bv = dv[aa]; best = aa; }
                }
                if (best < 0) break;
                used[best] = true;
                ssel[bb][cnt++] = best;
            }
            scnt[bb] = cnt;
            smc[bb]  = m;
        }
    }
    __syncthreads();

    const int cnt = scnt[b];
    const int m   = smc[b];

    float acc[C];
#pragma unroll
    for (int c = 0; c < C; c++) acc[c] = 0.f;

    for (int j = 0; j < cnt; j++) {
        const int a = ssel[b][j];
        const float* __restrict__ lp = auged_logits + ((size_t)(b * A + a) * C) * HW + p;
        float l[C];
        float mx = -INFINITY;
#pragma unroll
        for (int c = 0; c < C; c++) { l[c] = lp[(size_t)c * HW]; mx = fmaxf(mx, l[c]); }
        float ssum = 0.f;
#pragma unroll
        for (int c = 0; c < C; c++) { l[c] = __expf(l[c] - mx); ssum += l[c]; }
        float inv = 1.0f / ssum;
#pragma unroll
        for (int c = 0; c < C; c++) acc[c] = fmaf(l[c], inv, acc[c]);
    }

    const float invc = 1.0f / (float)max(cnt, 1);

    // knn label = argmax over averaged softmax (first index on tie)
    int knn = 0; float bv = acc[0];
#pragma unroll
    for (int c = 1; c < C; c++) { if (acc[c] > bv) { bv = acc[c]; knn = c; } }

    int refined = (pmask && m > 0) ? knn : pl;
    out[pix] = (float)refined;

    // avg_soft output (coalesced per-class streams)
    float* __restrict__ oavg = out + (size_t)B * HW;
#pragma unroll
    for (int c = 0; c < C; c++)
        oavg[((size_t)b * C + c) * HW + p] = acc[c] * invc;
}

// ---------------- launch ----------------
extern "C" void kernel_launch(void* const* d_in, const int* in_sizes, int n_in,
                              void* d_out, int out_size) {
    const float* source_queue = (const float*)d_in[0];
    const float* tgt_feat     = (const float*)d_in[1];
    const float* tgt_logits   = (const float*)d_in[2];
    const float* auged_feat   = (const float*)d_in[3];
    const float* auged_logits = (const float*)d_in[4];
    const int*   pseudo_label = (const int*)d_in[5];
    const int*   kptr         = (n_in > 6) ? (const int*)d_in[6] : nullptr;
    float* out = (float*)d_out;

    k_dots_tt<<<NDOT + CONFB + NTT, 128>>>(source_queue, tgt_feat, tgt_logits);
    k_d2     <<<32 * S_D2, 256>>>(auged_feat, source_queue);
    k_final  <<<(B * HW) / 256, 256>>>(auged_logits, pseudo_label, kptr, out);
    (void)in_sizes; (void)out_size;
}

// round 12
// speedup vs baseline: 1.1529x; 1.0226x over previous
#include <cuda_runtime.h>
#include <math.h>

// Problem dims (fixed by the dataset)
#define Q   512
#define D   131072           // 512*16*16
#define D4  (D/4)            // 32768 float4
#define B   2
#define A   16
#define C   19
#define HW  65536            // 256*256
#define REFINE_CONF 0.968f

// k_dots tiling: 8 rows/block, register-held tgt
#define CH     2048          // float4 per D-chunk
#define S_DOTS (D4/CH)       // 16 D-splits
#define RPB    8             // queue rows per block
#define ROWG   (Q/RPB)       // 64 row-groups
#define NDOT   (S_DOTS*ROWG) // 1024 dot blocks
#define CONFB  512           // confidence blocks: 256 pixels each (2/thread)
#define NTT    32            // tt blocks
// k_d2 tiling
#define S_TT   16
#define CHTT   (D4/S_TT)     // 2048 float4
#define S_D2   16
#define CH2    (D4/S_D2)     // 2048 float4

// ---------------- scratch (no allocations allowed) ----------------
__device__ float g_pu[S_DOTS][Q];         // partial ||q||^2 - 2 q.t0
__device__ float g_pw[S_DOTS][Q];         // partial q.(t0 - t1)
__device__ float g_ptt[S_TT][B];          // partial ||tgt_b||^2
__device__ float g_cd2[B];                // closest distance^2 (redundantly written)
__device__ float g_pd2[S_D2][B][A];       // partial ||aug - closest||^2
__device__ unsigned char g_pmask[B * HW]; // low-confidence mask

__device__ __forceinline__ float dot4(float4 a, float4 b, float acc) {
    return fmaf(a.x, b.x, fmaf(a.y, b.y, fmaf(a.z, b.z, fmaf(a.w, b.w, acc))));
}

// ---------------- kernel 1: queue dots (u/w form, 64-reg budget) + conf mask + tt ----------------
__global__ __launch_bounds__(128, 8) void k_dots_tt(const float* __restrict__ queue,
                                                    const float* __restrict__ tgt,
                                                    const float* __restrict__ tgt_logits) {
    const int bid = blockIdx.x;
    const int tid = threadIdx.x;
    const int lane = tid & 31, warp = tid >> 5;
    __shared__ float red[RPB * 2][128];           // 8 KB

    if (bid < NDOT) {
        const int s    = bid >> 6;                // D-split (ROWG = 64)
        const int rowg = bid & 63;
        const int q0   = rowg * RPB;
        const int i0   = s * CH;
        const float4* __restrict__ qf = (const float4*)queue;
        const float4* __restrict__ tf = (const float4*)tgt;

        float acc[RPB * 2];                       // [r*2+0]=u, [r*2+1]=w
#pragma unroll
        for (int v = 0; v < RPB * 2; v++) acc[v] = 0.f;

        const float4* __restrict__ qbase = qf + (size_t)q0 * D4 + i0 + tid;
        const float4* __restrict__ tbase = tf + i0 + tid;

        for (int off = 0; off < CH; off += 128) {
            // 10 front-batched independent loads, ALL live simultaneously (64-reg budget).
            // Queue (DRAM, long latency) issued first; tgt (L2-hot) last.
            float4 qv[RPB];
#pragma unroll
            for (int r = 0; r < RPB; r++) qv[r] = qbase[(size_t)r * D4 + off];
            float4 t0 = tbase[off];
            float4 t1 = tbase[D4 + off];
            float4 dv;                            // t0 - t1 (shared across rows)
            dv.x = t0.x - t1.x; dv.y = t0.y - t1.y;
            dv.z = t0.z - t1.z; dv.w = t0.w - t1.w;
#pragma unroll
            for (int r = 0; r < RPB; r++) {
                float4 e;                         // q - 2*t0
                e.x = fmaf(-2.f, t0.x, qv[r].x);
                e.y = fmaf(-2.f, t0.y, qv[r].y);
                e.z = fmaf(-2.f, t0.z, qv[r].z);
                e.w = fmaf(-2.f, t0.w, qv[r].w);
                acc[r * 2 + 0] = dot4(qv[r], e,  acc[r * 2 + 0]);
                acc[r * 2 + 1] = dot4(qv[r], dv, acc[r * 2 + 1]);
            }
        }

#pragma unroll
        for (int v = 0; v < RPB * 2; v++) red[v][tid] = acc[v];
        __syncthreads();
        // 4 warps x 4 values each
#pragma unroll
        for (int c = 0; c < 4; c++) {
            const int v = warp * 4 + c;           // 0..15
            float ssum = red[v][lane] + red[v][lane + 32] + red[v][lane + 64] + red[v][lane + 96];
#pragma unroll
            for (int o = 16; o > 0; o >>= 1) ssum += __shfl_down_sync(0xFFFFFFFFu, ssum, o);
            if (lane == 0) {
                const int r = v >> 1;
                if ((v & 1) == 0) g_pu[s][q0 + r] = ssum;
                else              g_pw[s][q0 + r] = ssum;
            }
        }
    } else if (bid < NDOT + CONFB) {
        // confidence blocks: 19 INDEPENDENT loads, then reduce. Tail filler.
        const int cb = bid - NDOT;
#pragma unroll
        for (int u = 0; u < 2; u++) {
            const int pix = cb * 256 + u * 128 + tid;
            const int b = pix >> 16;
            const int p = pix & (HW - 1);
            const float* __restrict__ tp = tgt_logits + (size_t)b * C * HW + p;
            float tl[C];
#pragma unroll
            for (int c = 0; c < C; c++) tl[c] = tp[(size_t)c * HW];
            float mx = tl[0];
#pragma unroll
            for (int c = 1; c < C; c++) mx = fmaxf(mx, tl[c]);
            float sum = 0.f;
#pragma unroll
            for (int c = 0; c < C; c++) sum += __expf(tl[c] - mx);
            g_pmask[pix] = ((1.0f / sum) < REFINE_CONF) ? 1 : 0;
        }
    } else {
        // tt blocks: 32 of them, (sc, b)
        const int s2 = bid - NDOT - CONFB;
        const int b  = s2 & 1;
        const int sc = s2 >> 1;                   // 0..15
        const float4* __restrict__ tf = (const float4*)tgt + (size_t)b * D4 + sc * CHTT;
        float sum = 0.f;
        for (int i = tid; i < CHTT; i += 128) {
            float4 t = tf[i];
            sum = dot4(t, t, sum);
        }
#pragma unroll
        for (int o = 16; o > 0; o >>= 1) sum += __shfl_down_sync(0xFFFFFFFFu, sum, o);
        if (lane == 0) red[0][warp] = sum;
        __syncthreads();
        if (tid < 4) {
            sum = red[0][tid];
#pragma unroll
            for (int o = 2; o > 0; o >>= 1) sum += __shfl_down_sync(0xFu, sum, o);
            if (tid == 0) g_ptt[sc][b] = sum;
        }
    }
}

// ---------------- kernel 2: per-block argmin preamble + d2 partials ----------------
__global__ __launch_bounds__(256) void k_d2(const float* __restrict__ auged,
                                            const float* __restrict__ queue) {
    const int pair = blockIdx.x & 31;            // b*A + a
    const int s    = blockIdx.x >> 5;            // 0..S_D2-1
    const int b = pair >> 4;
    const int a = pair & 15;
    const int tid = threadIdx.x;
    const int lane = tid & 31, warp = tid >> 5;

    __shared__ float tts[B];
    __shared__ float sv[256];
    __shared__ int   si[256];
    __shared__ int   s_imin[B];

    // ---- preamble: recompute argmin from L2-hot partials (no cross-block sync) ----
    if (tid < B) {
        float t = 0.f;
#pragma unroll
        for (int ss = 0; ss < S_TT; ss++) t += g_ptt[ss][tid];
        tts[tid] = t;
    }
    // per-thread sums for q = tid and q + 256
    float u1 = 0.f, w1 = 0.f, u2 = 0.f, w2 = 0.f;
#pragma unroll
    for (int ss = 0; ss < S_DOTS; ss++) {
        u1 += g_pu[ss][tid];
        w1 += g_pw[ss][tid];
        u2 += g_pu[ss][tid + 256];
        w2 += g_pw[ss][tid + 256];
    }
    __syncthreads();
#pragma unroll
    for (int bb = 0; bb < B; bb++) {
        float v1, v2;
        if (bb == 0) { v1 = u1 + tts[0];               v2 = u2 + tts[0]; }
        else         { v1 = fmaf(2.f, w1, u1) + tts[1]; v2 = fmaf(2.f, w2, u2) + tts[1]; }
        float bv; int bi;
        if (v2 < v1) { bv = v2; bi = tid + 256; } else { bv = v1; bi = tid; }
        sv[tid] = bv; si[tid] = bi;
        __syncthreads();
        for (int st = 128; st > 0; st >>= 1) {
            if (tid < st) {
                float ov = sv[tid + st]; int oi = si[tid + st];
                if (ov < sv[tid] || (ov == sv[tid] && oi < si[tid])) { sv[tid] = ov; si[tid] = oi; }
            }
            __syncthreads();
        }
        if (tid == 0) {
            s_imin[bb] = si[0];
            g_cd2[bb]  = sv[0];   // identical value from every block: benign race
        }
        __syncthreads();
    }

    // ---- main: ||aug[b,a] - closest_b||^2 over this block's D-chunk ----
    const int im = s_imin[b];
    const int i0 = s * CH2;                      // 2048 float4 per split
    const float4* __restrict__ af = (const float4*)(auged + ((size_t)b * A + a) * D) + i0 + tid;
    const float4* __restrict__ cf = (const float4*)(queue + (size_t)im * D) + i0 + tid;

    float sacc = 0.f;
#pragma unroll
    for (int it = 0; it < 2; it++) {
        const int off = it * 1024;
        float4 av[4], cv[4];
#pragma unroll
        for (int u = 0; u < 4; u++) av[u] = af[off + u * 256];
#pragma unroll
        for (int u = 0; u < 4; u++) cv[u] = cf[off + u * 256];
#pragma unroll
        for (int u = 0; u < 4; u++) {
            float dx = av[u].x - cv[u].x, dy = av[u].y - cv[u].y;
            float dz = av[u].z - cv[u].z, dw = av[u].w - cv[u].w;
            sacc = fmaf(dx, dx, fmaf(dy, dy, fmaf(dz, dz, fmaf(dw, dw, sacc))));
        }
    }
#pragma unroll
    for (int o = 16; o > 0; o >>= 1) sacc += __shfl_down_sync(0xFFFFFFFFu, sacc, o);
    if (lane == 0) sv[warp] = sacc;
    __syncthreads();
    if (tid < 8) {
        sacc = sv[tid];
#pragma unroll
        for (int o = 4; o > 0; o >>= 1) sacc += __shfl_down_sync(0xFFu, sacc, o);
        if (tid == 0) g_pd2[s][b][a] = sacc;
    }
}

// ---------------- kernel 3: parallel select preamble + gather/argmax/gate ----------------
__global__ __launch_bounds__(256) void k_final(const float* __restrict__ auged_logits,
                                               const int*   __restrict__ pseudo,
                                               const int*   __restrict__ kptr,
                                               float* __restrict__ out) {
    __shared__ float d2s[B][A];
    __shared__ int   ssel[B][16];
    __shared__ int   scnt[B];
    __shared__ int   smc[B];
    const int tid = threadIdx.x;

    const int pix = blockIdx.x * 256 + tid;   // < B*HW
    const int b = pix >> 16;
    const int p = pix & (HW - 1);

    // issue independent loads before the preamble barriers
    const int  pl    = pseudo[(size_t)b * HW + p];
    const bool pmask = g_pmask[pix] != 0;

    // parallel d2 reduce: 8 threads per (b,a) pair, 2 loads each + width-8 shuffle
    {
        const int pairid = tid >> 3;          // 0..31
        const int sub    = tid & 7;
        const int bb = pairid >> 4, aa = pairid & 15;
        float v = g_pd2[sub][bb][aa] + g_pd2[sub + 8][bb][aa];
#pragma unroll
        for (int o = 4; o > 0; o >>= 1) v += __shfl_down_sync(0xFFFFFFFFu, v, o, 8);
        if (sub == 0) d2s[bb][aa] = v;
    }
    __syncthreads();
    if (tid == 0) {
        int k = kptr ? kptr[0] : 5;
        if (k > 16) k = 16;
        if (k < 0)  k = 0;
        for (int bb = 0; bb < B; bb++) {
            float cd = g_cd2[bb];
            float dv[16];
            int m = 0;
#pragma unroll
            for (int aa = 0; aa < A; aa++) {
                dv[aa] = d2s[bb][aa];
                if (dv[aa] <= cd) m++;
            }
            bool used[16] = {false};
            int cnt = 0;
            for (int j = 0; j < k; j++) {
                int best = -1; float bv = INFINITY;
                for (int aa = 0; aa < A; aa++) {
                    if (!used[aa] && dv[aa] <= cd && dv[aa] < bv) { bv = dv[aa]; best = aa; }
                }
                if (best < 0) break;
                used[best] = true;
                ssel[bb][cnt++] = best;
            }
            scnt[bb] = cnt;
            smc[bb]  = m;
        }
    }
    __syncthreads();

    const int cnt = scnt[b];
    const int m   = smc[b];

    float acc[C];
#pragma unroll
    for (int c = 0; c < C; c++) acc[c] = 0.f;

    for (int j = 0; j < cnt; j++) {
        const int a = ssel[b][j];
        const float* __restrict__ lp = auged_logits + ((size_t)(b * A + a) * C) * HW + p;
        float l[C];
        float mx = -INFINITY;
#pragma unroll
        for (int c = 0; c < C; c++) { l[c] = lp[(size_t)c * HW]; mx = fmaxf(mx, l[c]); }
        float ssum = 0.f;
#pragma unroll
        for (int c = 0; c < C; c++) { l[c] = __expf(l[c] - mx); ssum += l[c]; }
        float inv = 1.0f / ssum;
#pragma unroll
        for (int c = 0; c < C; c++) acc[c] = fmaf(l[c], inv, acc[c]);
    }

    const float invc = 1.0f / (float)max(cnt, 1);

    // knn label = argmax over averaged softmax (first index on tie)
    int knn = 0; float bv = acc[0];
#pragma unroll
    for (int c = 1; c < C; c++) { if (acc[c] > bv) { bv = acc[c]; knn = c; } }

    int refined = (pmask && m > 0) ? knn : pl;
    out[pix] = (float)refined;

    // avg_soft output (coalesced per-class streams)
    float* __restrict__ oavg = out + (size_t)B * HW;
#pragma unroll
    for (int c = 0; c < C; c++)
        oavg[((size_t)b * C + c) * HW + p] = acc[c] * invc;
}

// ---------------- launch ----------------
extern "C" void kernel_launch(void* const* d_in, const int* in_sizes, int n_in,
                              void* d_out, int out_size) {
    const float* source_queue = (const float*)d_in[0];
    const float* tgt_feat     = (const float*)d_in[1];
    const float* tgt_logits   = (const float*)d_in[2];
    const float* auged_feat   = (const float*)d_in[3];
    const float* auged_logits = (const float*)d_in[4];
    const int*   pseudo_label = (const int*)d_in[5];
    const int*   kptr         = (n_in > 6) ? (const int*)d_in[6] : nullptr;
    float* out = (float*)d_out;

    k_dots_tt<<<NDOT + CONFB + NTT, 128>>>(source_queue, tgt_feat, tgt_logits);
    k_d2     <<<32 * S_D2, 256>>>(auged_feat, source_queue);
    k_final  <<<(B * HW) / 256, 256>>>(auged_logits, pseudo_label, kptr, out);
    (void)in_sizes; (void)out_size;
}

// round 13
// speedup vs baseline: 1.1618x; 1.0078x over previous
#include <cuda_runtime.h>
#include <math.h>

// Problem dims (fixed by the dataset)
#define Q   512
#define D   131072           // 512*16*16
#define D4  (D/4)            // 32768 float4
#define B   2
#define A   16
#define C   19
#define HW  65536            // 256*256
#define REFINE_CONF 0.968f

// k1 tiling: 8 rows/block, register-held tgt; persistent single wave
#define CH     2048          // float4 per D-chunk
#define S_DOTS (D4/CH)       // 16 D-splits
#define RPB    8             // queue rows per block
#define ROWG   (Q/RPB)       // 64 row-groups
#define NDOT   (S_DOTS*ROWG) // 1024 dot items
#define CONFB  512           // conf items: 256 pixels each (2/thread)
#define NTT    32            // tt items
#define NITEMS (NDOT+CONFB+NTT)  // 1568 work items
#define NK1    1184          // 148 SMs x 8 blocks: exactly one wave
// k_d2 tiling
#define S_TT   16
#define CHTT   (D4/S_TT)     // 2048 float4
#define S_D2   16
#define CH2    (D4/S_D2)     // 2048 float4

// ---------------- scratch (no allocations allowed) ----------------
__device__ float g_pu[S_DOTS][Q];         // partial ||q||^2 - 2 q.t0
__device__ float g_pw[S_DOTS][Q];         // partial q.(t0 - t1)
__device__ float g_ptt[S_TT][B];          // partial ||tgt_b||^2
__device__ float g_cd2[B];                // closest distance^2 (redundantly written)
__device__ float g_pd2[S_D2][B][A];       // partial ||aug - closest||^2
__device__ unsigned char g_pmask[B * HW]; // low-confidence mask

__device__ __forceinline__ float dot4(float4 a, float4 b, float acc) {
    return fmaf(a.x, b.x, fmaf(a.y, b.y, fmaf(a.z, b.z, fmaf(a.w, b.w, acc))));
}

// ---------------- kernel 1: persistent single-wave: dots + conf + tt ----------------
__global__ __launch_bounds__(128, 8) void k_dots_tt(const float* __restrict__ queue,
                                                    const float* __restrict__ tgt,
                                                    const float* __restrict__ tgt_logits) {
    const int tid = threadIdx.x;
    const int lane = tid & 31, warp = tid >> 5;
    __shared__ float red[RPB * 2][128];           // 8 KB

    for (int item = blockIdx.x; item < NITEMS; item += NK1) {
        if (item < NDOT) {
            const int s    = item >> 6;           // D-split (ROWG = 64)
            const int rowg = item & 63;
            const int q0   = rowg * RPB;
            const int i0   = s * CH;
            const float4* __restrict__ qbase = (const float4*)queue + (size_t)q0 * D4 + i0 + tid;
            const float4* __restrict__ tbase = (const float4*)tgt + i0 + tid;

            float acc[RPB * 2];                   // [r*2+0]=u, [r*2+1]=w
#pragma unroll
            for (int v = 0; v < RPB * 2; v++) acc[v] = 0.f;

            for (int off = 0; off < CH; off += 128) {
                // 10 front-batched independent loads; queue (DRAM) first, tgt (L2) last.
                float4 qv[RPB];
#pragma unroll
                for (int r = 0; r < RPB; r++) qv[r] = qbase[(size_t)r * D4 + off];
                float4 t0 = tbase[off];
                float4 t1 = tbase[D4 + off];
                float4 dv;                        // t0 - t1 (shared across rows)
                dv.x = t0.x - t1.x; dv.y = t0.y - t1.y;
                dv.z = t0.z - t1.z; dv.w = t0.w - t1.w;
#pragma unroll
                for (int r = 0; r < RPB; r++) {
                    float4 e;                     // q - 2*t0
                    e.x = fmaf(-2.f, t0.x, qv[r].x);
                    e.y = fmaf(-2.f, t0.y, qv[r].y);
                    e.z = fmaf(-2.f, t0.z, qv[r].z);
                    e.w = fmaf(-2.f, t0.w, qv[r].w);
                    acc[r * 2 + 0] = dot4(qv[r], e,  acc[r * 2 + 0]);
                    acc[r * 2 + 1] = dot4(qv[r], dv, acc[r * 2 + 1]);
                }
            }

#pragma unroll
            for (int v = 0; v < RPB * 2; v++) red[v][tid] = acc[v];
            __syncthreads();
            // 4 warps x 4 values each
#pragma unroll
            for (int c = 0; c < 4; c++) {
                const int v = warp * 4 + c;       // 0..15
                float ssum = red[v][lane] + red[v][lane + 32] + red[v][lane + 64] + red[v][lane + 96];
#pragma unroll
                for (int o = 16; o > 0; o >>= 1) ssum += __shfl_down_sync(0xFFFFFFFFu, ssum, o);
                if (lane == 0) {
                    const int r = v >> 1;
                    if ((v & 1) == 0) g_pu[s][q0 + r] = ssum;
                    else              g_pw[s][q0 + r] = ssum;
                }
            }
        } else if (item < NDOT + CONFB) {
            // confidence item: 19 INDEPENDENT loads per pixel, two pixels/thread
            const int cb = item - NDOT;
#pragma unroll
            for (int u = 0; u < 2; u++) {
                const int pix = cb * 256 + u * 128 + tid;
                const int b = pix >> 16;
                const int p = pix & (HW - 1);
                const float* __restrict__ tp = tgt_logits + (size_t)b * C * HW + p;
                float tl[C];
#pragma unroll
                for (int c = 0; c < C; c++) tl[c] = tp[(size_t)c * HW];
                float mx = tl[0];
#pragma unroll
                for (int c = 1; c < C; c++) mx = fmaxf(mx, tl[c]);
                float sum = 0.f;
#pragma unroll
                for (int c = 0; c < C; c++) sum += __expf(tl[c] - mx);
                g_pmask[pix] = ((1.0f / sum) < REFINE_CONF) ? 1 : 0;
            }
        } else {
            // tt item
            const int s2 = item - NDOT - CONFB;
            const int b  = s2 & 1;
            const int sc = s2 >> 1;               // 0..15
            const float4* __restrict__ tf = (const float4*)tgt + (size_t)b * D4 + sc * CHTT;
            float sum = 0.f;
            for (int i = tid; i < CHTT; i += 128) {
                float4 t = tf[i];
                sum = dot4(t, t, sum);
            }
#pragma unroll
            for (int o = 16; o > 0; o >>= 1) sum += __shfl_down_sync(0xFFFFFFFFu, sum, o);
            if (lane == 0) red[0][warp] = sum;
            __syncthreads();
            if (tid < 4) {
                sum = red[0][tid];
#pragma unroll
                for (int o = 2; o > 0; o >>= 1) sum += __shfl_down_sync(0xFu, sum, o);
                if (tid == 0) g_ptt[sc][b] = sum;
            }
        }
        __syncthreads();   // red[] safe for reuse next item
    }
}

// ---------------- kernel 2: per-block argmin preamble + d2 partials ----------------
__global__ __launch_bounds__(256) void k_d2(const float* __restrict__ auged,
                                            const float* __restrict__ queue) {
    const int pair = blockIdx.x & 31;            // b*A + a
    const int s    = blockIdx.x >> 5;            // 0..S_D2-1
    const int b = pair >> 4;
    const int a = pair & 15;
    const int tid = threadIdx.x;
    const int lane = tid & 31, warp = tid >> 5;

    __shared__ float tts[B];
    __shared__ float sv[256];
    __shared__ int   si[256];
    __shared__ int   s_imin[B];

    // ---- preamble: recompute argmin from L2-hot partials (no cross-block sync) ----
    if (tid < B) {
        float t = 0.f;
#pragma unroll
        for (int ss = 0; ss < S_TT; ss++) t += g_ptt[ss][tid];
        tts[tid] = t;
    }
    float u1 = 0.f, w1 = 0.f, u2 = 0.f, w2 = 0.f;
#pragma unroll
    for (int ss = 0; ss < S_DOTS; ss++) {
        u1 += g_pu[ss][tid];
        w1 += g_pw[ss][tid];
        u2 += g_pu[ss][tid + 256];
        w2 += g_pw[ss][tid + 256];
    }
    __syncthreads();
#pragma unroll
    for (int bb = 0; bb < B; bb++) {
        float v1, v2;
        if (bb == 0) { v1 = u1 + tts[0];                v2 = u2 + tts[0]; }
        else         { v1 = fmaf(2.f, w1, u1) + tts[1]; v2 = fmaf(2.f, w2, u2) + tts[1]; }
        float bv; int bi;
        if (v2 < v1) { bv = v2; bi = tid + 256; } else { bv = v1; bi = tid; }
        sv[tid] = bv; si[tid] = bi;
        __syncthreads();
        for (int st = 128; st > 0; st >>= 1) {
            if (tid < st) {
                float ov = sv[tid + st]; int oi = si[tid + st];
                if (ov < sv[tid] || (ov == sv[tid] && oi < si[tid])) { sv[tid] = ov; si[tid] = oi; }
            }
            __syncthreads();
        }
        if (tid == 0) {
            s_imin[bb] = si[0];
            g_cd2[bb]  = sv[0];   // identical value from every block: benign race
        }
        __syncthreads();
    }

    // ---- main: ||aug[b,a] - closest_b||^2 over this block's D-chunk ----
    const int im = s_imin[b];
    const int i0 = s * CH2;                      // 2048 float4 per split
    const float4* __restrict__ af = (const float4*)(auged + ((size_t)b * A + a) * D) + i0 + tid;
    const float4* __restrict__ cf = (const float4*)(queue + (size_t)im * D) + i0 + tid;

    float sacc = 0.f;
#pragma unroll
    for (int it = 0; it < 2; it++) {
        const int off = it * 1024;
        float4 av[4], cv[4];
#pragma unroll
        for (int u = 0; u < 4; u++) av[u] = af[off + u * 256];
#pragma unroll
        for (int u = 0; u < 4; u++) cv[u] = cf[off + u * 256];
#pragma unroll
        for (int u = 0; u < 4; u++) {
            float dx = av[u].x - cv[u].x, dy = av[u].y - cv[u].y;
            float dz = av[u].z - cv[u].z, dw = av[u].w - cv[u].w;
            sacc = fmaf(dx, dx, fmaf(dy, dy, fmaf(dz, dz, fmaf(dw, dw, sacc))));
        }
    }
#pragma unroll
    for (int o = 16; o > 0; o >>= 1) sacc += __shfl_down_sync(0xFFFFFFFFu, sacc, o);
    if (lane == 0) sv[warp] = sacc;
    __syncthreads();
    if (tid < 8) {
        sacc = sv[tid];
#pragma unroll
        for (int o = 4; o > 0; o >>= 1) sacc += __shfl_down_sync(0xFFu, sacc, o);
        if (tid == 0) g_pd2[s][b][a] = sacc;
    }
}

// ---------------- kernel 3: select preamble + gather/argmax/gate, 2 px/thread ----------------
__global__ __launch_bounds__(256) void k_final(const float* __restrict__ auged_logits,
                                               const int*   __restrict__ pseudo,
                                               const int*   __restrict__ kptr,
                                               float* __restrict__ out) {
    __shared__ float d2s[B][A];
    __shared__ int   ssel[B][16];
    __shared__ int   scnt[B];
    __shared__ int   smc[B];
    const int tid = threadIdx.x;

    const int base = (blockIdx.x * 256 + tid) * 2;   // first of 2 consecutive pixels
    const int b = base >> 16;
    const int p = base & (HW - 1);

    // issue independent loads before the preamble barriers
    const int2 pl2 = ((const int2*)pseudo)[base >> 1];
    const unsigned char pm0 = g_pmask[base];
    const unsigned char pm1 = g_pmask[base + 1];

    // parallel d2 reduce: 8 threads per (b,a) pair, 2 loads each + width-8 shuffle
    {
        const int pairid = tid >> 3;          // 0..31
        const int sub    = tid & 7;
        const int bb = pairid >> 4, aa = pairid & 15;
        float v = g_pd2[sub][bb][aa] + g_pd2[sub + 8][bb][aa];
#pragma unroll
        for (int o = 4; o > 0; o >>= 1) v += __shfl_down_sync(0xFFFFFFFFu, v, o, 8);
        if (sub == 0) d2s[bb][aa] = v;
    }
    __syncthreads();
    if (tid == 0) {
        int k = kptr ? kptr[0] : 5;
        if (k > 16) k = 16;
        if (k < 0)  k = 0;
        for (int bb = 0; bb < B; bb++) {
            float cd = g_cd2[bb];
            float dv[16];
            int m = 0;
#pragma unroll
            for (int aa = 0; aa < A; aa++) {
                dv[aa] = d2s[bb][aa];
                if (dv[aa] <= cd) m++;
            }
            bool used[16] = {false};
            int cnt = 0;
            for (int j = 0; j < k; j++) {
                int best = -1; float bv = INFINITY;
                for (int aa = 0; aa < A; aa++) {
                    if (!used[aa] && dv[aa] <= cd && dv[aa] < bv) { bv = dv[aa]; best = aa; }
                }
                if (best < 0) break;
                used[best] = true;
                ssel[bb][cnt++] = best;
            }
            scnt[bb] = cnt;
            smc[bb]  = m;
        }
    }
    __syncthreads();

    const int cnt = scnt[b];
    const int m   = smc[b];

    float acc0[C], acc1[C];
#pragma unroll
    for (int c = 0; c < C; c++) { acc0[c] = 0.f; acc1[c] = 0.f; }

    for (int j = 0; j < cnt; j++) {
        const int a = ssel[b][j];
        const float* __restrict__ lp = auged_logits + ((size_t)(b * A + a) * C) * HW + p;
        float l0[C], l1[C];
        float mx0 = -INFINITY, mx1 = -INFINITY;
#pragma unroll
        for (int c = 0; c < C; c++) {
            float2 lv = *(const float2*)(lp + (size_t)c * HW);
            l0[c] = lv.x; l1[c] = lv.y;
            mx0 = fmaxf(mx0, lv.x); mx1 = fmaxf(mx1, lv.y);
        }
        float s0 = 0.f, s1 = 0.f;
#pragma unroll
        for (int c = 0; c < C; c++) {
            l0[c] = __expf(l0[c] - mx0); s0 += l0[c];
            l1[c] = __expf(l1[c] - mx1); s1 += l1[c];
        }
        float inv0 = 1.0f / s0, inv1 = 1.0f / s1;
#pragma unroll
        for (int c = 0; c < C; c++) {
            acc0[c] = fmaf(l0[c], inv0, acc0[c]);
            acc1[c] = fmaf(l1[c], inv1, acc1[c]);
        }
    }

    const float invc = 1.0f / (float)max(cnt, 1);

    int knn0 = 0, knn1 = 0;
    float bv0 = acc0[0], bv1 = acc1[0];
#pragma unroll
    for (int c = 1; c < C; c++) {
        if (acc0[c] > bv0) { bv0 = acc0[c]; knn0 = c; }
        if (acc1[c] > bv1) { bv1 = acc1[c]; knn1 = c; }
    }

    const bool sel = (m > 0);
    float r0 = (float)((pm0 && sel) ? knn0 : pl2.x);
    float r1 = (float)((pm1 && sel) ? knn1 : pl2.y);
    ((float2*)out)[base >> 1] = make_float2(r0, r1);

    float* __restrict__ oavg = out + (size_t)B * HW;
#pragma unroll
    for (int c = 0; c < C; c++)
        *(float2*)(oavg + ((size_t)b * C + c) * HW + p) = make_float2(acc0[c] * invc, acc1[c] * invc);
}

// ---------------- launch ----------------
extern "C" void kernel_launch(void* const* d_in, const int* in_sizes, int n_in,
                              void* d_out, int out_size) {
    const float* source_queue = (const float*)d_in[0];
    const float* tgt_feat     = (const float*)d_in[1];
    const float* tgt_logits   = (const float*)d_in[2];
    const float* auged_feat   = (const float*)d_in[3];
    const float* auged_logits = (const float*)d_in[4];
    const int*   pseudo_label = (const int*)d_in[5];
    const int*   kptr         = (n_in > 6) ? (const int*)d_in[6] : nullptr;
    float* out = (float*)d_out;

    k_dots_tt<<<NK1, 128>>>(source_queue, tgt_feat, tgt_logits);
    k_d2     <<<32 * S_D2, 256>>>(auged_feat, source_queue);
    k_final  <<<(B * HW) / 512, 256>>>(auged_logits, pseudo_label, kptr, out);
    (void)in_sizes; (void)out_size;
}

// round 14
// speedup vs baseline: 1.1996x; 1.0325x over previous
#include <cuda_runtime.h>
#include <math.h>

// Problem dims (fixed by the dataset)
#define Q   512
#define D   131072           // 512*16*16
#define D4  (D/4)            // 32768 float4
#define B   2
#define A   16
#define C   19
#define HW  65536            // 256*256
#define REFINE_CONF 0.968f

// k1 tiling: 8 rows/block, register-held tgt; persistent single wave, 128KB quanta
#define CH     1024          // float4 per D-chunk (128KB dot quantum)
#define S_DOTS (D4/CH)       // 32 D-splits
#define RPB    8             // queue rows per item
#define ROWG   (Q/RPB)       // 64 row-groups
#define NDOT   (S_DOTS*ROWG) // 2048 dot items
#define CONFB  512           // conf items: 256 pixels each (2/thread)
#define NTT    32            // tt items
#define NITEMS (NDOT+CONFB+NTT)  // 2592 work items
#define NK1    1184          // 148 SMs x 8 blocks: exactly one wave
// k_d2 tiling
#define S_TT   16
#define CHTT   (D4/S_TT)     // 2048 float4
#define S_D2   16
#define CH2    (D4/S_D2)     // 2048 float4

// ---------------- scratch (no allocations allowed) ----------------
__device__ float g_pu[S_DOTS][Q];         // partial ||q||^2 - 2 q.t0
__device__ float g_pw[S_DOTS][Q];         // partial q.(t0 - t1)
__device__ float g_ptt[S_TT][B];          // partial ||tgt_b||^2
__device__ float g_cd2[B];                // closest distance^2 (redundantly written)
__device__ float g_pd2[S_D2][B][A];       // partial ||aug - closest||^2
__device__ unsigned char g_pmask[B * HW]; // low-confidence mask

__device__ __forceinline__ float dot4(float4 a, float4 b, float acc) {
    return fmaf(a.x, b.x, fmaf(a.y, b.y, fmaf(a.z, b.z, fmaf(a.w, b.w, acc))));
}

// ---------------- kernel 1: persistent single-wave: dots + conf + tt ----------------
__global__ __launch_bounds__(128, 8) void k_dots_tt(const float* __restrict__ queue,
                                                    const float* __restrict__ tgt,
                                                    const float* __restrict__ tgt_logits) {
    const int tid = threadIdx.x;
    const int lane = tid & 31, warp = tid >> 5;
    __shared__ float red[RPB * 2][128];           // 8 KB

    for (int item = blockIdx.x; item < NITEMS; item += NK1) {
        if (item < NDOT) {
            const int s    = item >> 6;           // D-split (ROWG = 64)
            const int rowg = item & 63;
            const int q0   = rowg * RPB;
            const int i0   = s * CH;
            const float4* __restrict__ qbase = (const float4*)queue + (size_t)q0 * D4 + i0 + tid;
            const float4* __restrict__ tbase = (const float4*)tgt + i0 + tid;

            float acc[RPB * 2];                   // [r*2+0]=u, [r*2+1]=w
#pragma unroll
            for (int v = 0; v < RPB * 2; v++) acc[v] = 0.f;

#pragma unroll
            for (int off = 0; off < CH; off += 128) {
                // 10 front-batched independent loads; queue (DRAM) first, tgt (L2) last.
                float4 qv[RPB];
#pragma unroll
                for (int r = 0; r < RPB; r++) qv[r] = qbase[(size_t)r * D4 + off];
                float4 t0 = tbase[off];
                float4 t1 = tbase[D4 + off];
                float4 dv;                        // t0 - t1 (shared across rows)
                dv.x = t0.x - t1.x; dv.y = t0.y - t1.y;
                dv.z = t0.z - t1.z; dv.w = t0.w - t1.w;
#pragma unroll
                for (int r = 0; r < RPB; r++) {
                    float4 e;                     // q - 2*t0
                    e.x = fmaf(-2.f, t0.x, qv[r].x);
                    e.y = fmaf(-2.f, t0.y, qv[r].y);
                    e.z = fmaf(-2.f, t0.z, qv[r].z);
                    e.w = fmaf(-2.f, t0.w, qv[r].w);
                    acc[r * 2 + 0] = dot4(qv[r], e,  acc[r * 2 + 0]);
                    acc[r * 2 + 1] = dot4(qv[r], dv, acc[r * 2 + 1]);
                }
            }

#pragma unroll
            for (int v = 0; v < RPB * 2; v++) red[v][tid] = acc[v];
            __syncthreads();
            // 4 warps x 4 values each
#pragma unroll
            for (int c = 0; c < 4; c++) {
                const int v = warp * 4 + c;       // 0..15
                float ssum = red[v][lane] + red[v][lane + 32] + red[v][lane + 64] + red[v][lane + 96];
#pragma unroll
                for (int o = 16; o > 0; o >>= 1) ssum += __shfl_down_sync(0xFFFFFFFFu, ssum, o);
                if (lane == 0) {
                    const int r = v >> 1;
                    if ((v & 1) == 0) g_pu[s][q0 + r] = ssum;
                    else              g_pw[s][q0 + r] = ssum;
                }
            }
        } else if (item < NDOT + CONFB) {
            // confidence item: 19 INDEPENDENT loads per pixel, two pixels/thread
            const int cb = item - NDOT;
#pragma unroll
            for (int u = 0; u < 2; u++) {
                const int pix = cb * 256 + u * 128 + tid;
                const int b = pix >> 16;
                const int p = pix & (HW - 1);
                const float* __restrict__ tp = tgt_logits + (size_t)b * C * HW + p;
                float tl[C];
#pragma unroll
                for (int c = 0; c < C; c++) tl[c] = tp[(size_t)c * HW];
                float mx = tl[0];
#pragma unroll
                for (int c = 1; c < C; c++) mx = fmaxf(mx, tl[c]);
                float sum = 0.f;
#pragma unroll
                for (int c = 0; c < C; c++) sum += __expf(tl[c] - mx);
                g_pmask[pix] = ((1.0f / sum) < REFINE_CONF) ? 1 : 0;
            }
        } else {
            // tt item
            const int s2 = item - NDOT - CONFB;
            const int b  = s2 & 1;
            const int sc = s2 >> 1;               // 0..15
            const float4* __restrict__ tf = (const float4*)tgt + (size_t)b * D4 + sc * CHTT;
            float sum = 0.f;
            for (int i = tid; i < CHTT; i += 128) {
                float4 t = tf[i];
                sum = dot4(t, t, sum);
            }
#pragma unroll
            for (int o = 16; o > 0; o >>= 1) sum += __shfl_down_sync(0xFFFFFFFFu, sum, o);
            if (lane == 0) red[0][warp] = sum;
            __syncthreads();
            if (tid < 4) {
                sum = red[0][tid];
#pragma unroll
                for (int o = 2; o > 0; o >>= 1) sum += __shfl_down_sync(0xFu, sum, o);
                if (tid == 0) g_ptt[sc][b] = sum;
            }
        }
        __syncthreads();   // red[] safe for reuse next item
    }
}

// ---------------- kernel 2: per-block argmin preamble + d2 partials ----------------
__global__ __launch_bounds__(256) void k_d2(const float* __restrict__ auged,
                                            const float* __restrict__ queue) {
    const int pair = blockIdx.x & 31;            // b*A + a
    const int s    = blockIdx.x >> 5;            // 0..S_D2-1
    const int b = pair >> 4;
    const int a = pair & 15;
    const int tid = threadIdx.x;
    const int lane = tid & 31, warp = tid >> 5;

    __shared__ float tts[B];
    __shared__ float sv[256];
    __shared__ int   si[256];
    __shared__ int   s_imin[B];

    // ---- preamble: recompute argmin from L2-hot partials (no cross-block sync) ----
    if (tid < B) {
        float t = 0.f;
#pragma unroll
        for (int ss = 0; ss < S_TT; ss++) t += g_ptt[ss][tid];
        tts[tid] = t;
    }
    float u1 = 0.f, w1 = 0.f, u2 = 0.f, w2 = 0.f;
#pragma unroll
    for (int ss = 0; ss < S_DOTS; ss++) {
        u1 += g_pu[ss][tid];
        w1 += g_pw[ss][tid];
        u2 += g_pu[ss][tid + 256];
        w2 += g_pw[ss][tid + 256];
    }
    __syncthreads();
#pragma unroll
    for (int bb = 0; bb < B; bb++) {
        float v1, v2;
        if (bb == 0) { v1 = u1 + tts[0];                v2 = u2 + tts[0]; }
        else         { v1 = fmaf(2.f, w1, u1) + tts[1]; v2 = fmaf(2.f, w2, u2) + tts[1]; }
        float bv; int bi;
        if (v2 < v1) { bv = v2; bi = tid + 256; } else { bv = v1; bi = tid; }
        sv[tid] = bv; si[tid] = bi;
        __syncthreads();
        for (int st = 128; st > 0; st >>= 1) {
            if (tid < st) {
                float ov = sv[tid + st]; int oi = si[tid + st];
                if (ov < sv[tid] || (ov == sv[tid] && oi < si[tid])) { sv[tid] = ov; si[tid] = oi; }
            }
            __syncthreads();
        }
        if (tid == 0) {
            s_imin[bb] = si[0];
            g_cd2[bb]  = sv[0];   // identical value from every block: benign race
        }
        __syncthreads();
    }

    // ---- main: ||aug[b,a] - closest_b||^2 over this block's D-chunk ----
    const int im = s_imin[b];
    const int i0 = s * CH2;                      // 2048 float4 per split
    const float4* __restrict__ af = (const float4*)(auged + ((size_t)b * A + a) * D) + i0 + tid;
    const float4* __restrict__ cf = (const float4*)(queue + (size_t)im * D) + i0 + tid;

    float sacc = 0.f;
#pragma unroll
    for (int it = 0; it < 2; it++) {
        const int off = it * 1024;
        float4 av[4], cv[4];
#pragma unroll
        for (int u = 0; u < 4; u++) av[u] = af[off + u * 256];
#pragma unroll
        for (int u = 0; u < 4; u++) cv[u] = cf[off + u * 256];
#pragma unroll
        for (int u = 0; u < 4; u++) {
            float dx = av[u].x - cv[u].x, dy = av[u].y - cv[u].y;
            float dz = av[u].z - cv[u].z, dw = av[u].w - cv[u].w;
            sacc = fmaf(dx, dx, fmaf(dy, dy, fmaf(dz, dz, fmaf(dw, dw, sacc))));
        }
    }
#pragma unroll
    for (int o = 16; o > 0; o >>= 1) sacc += __shfl_down_sync(0xFFFFFFFFu, sacc, o);
    if (lane == 0) sv[warp] = sacc;
    __syncthreads();
    if (tid < 8) {
        sacc = sv[tid];
#pragma unroll
        for (int o = 4; o > 0; o >>= 1) sacc += __shfl_down_sync(0xFFu, sacc, o);
        if (tid == 0) g_pd2[s][b][a] = sacc;
    }
}

// ---------------- kernel 3: select preamble + gather/argmax/gate, 2 px/thread ----------------
__global__ __launch_bounds__(256) void k_final(const float* __restrict__ auged_logits,
                                               const int*   __restrict__ pseudo,
                                               const int*   __restrict__ kptr,
                                               float* __restrict__ out) {
    __shared__ float d2s[B][A];
    __shared__ int   ssel[B][16];
    __shared__ int   scnt[B];
    __shared__ int   smc[B];
    const int tid = threadIdx.x;

    const int base = (blockIdx.x * 256 + tid) * 2;   // first of 2 consecutive pixels
    const int b = base >> 16;
    const int p = base & (HW - 1);

    // issue independent loads before the preamble barriers
    const int2 pl2 = ((const int2*)pseudo)[base >> 1];
    const unsigned char pm0 = g_pmask[base];
    const unsigned char pm1 = g_pmask[base + 1];

    // parallel d2 reduce: 8 threads per (b,a) pair, 2 loads each + width-8 shuffle
    {
        const int pairid = tid >> 3;          // 0..31
        const int sub    = tid & 7;
        const int bb = pairid >> 4, aa = pairid & 15;
        float v = g_pd2[sub][bb][aa] + g_pd2[sub + 8][bb][aa];
#pragma unroll
        for (int o = 4; o > 0; o >>= 1) v += __shfl_down_sync(0xFFFFFFFFu, v, o, 8);
        if (sub == 0) d2s[bb][aa] = v;
    }
    __syncthreads();
    if (tid == 0) {
        int k = kptr ? kptr[0] : 5;
        if (k > 16) k = 16;
        if (k < 0)  k = 0;
        for (int bb = 0; bb < B; bb++) {
            float cd = g_cd2[bb];
            float dv[16];
            int m = 0;
#pragma unroll
            for (int aa = 0; aa < A; aa++) {
                dv[aa] = d2s[bb][aa];
                if (dv[aa] <= cd) m++;
            }
            bool used[16] = {false};
            int cnt = 0;
            for (int j = 0; j < k; j++) {
                int best = -1; float bv = INFINITY;
                for (int aa = 0; aa < A; aa++) {
                    if (!used[aa] && dv[aa] <= cd && dv[aa] < bv) { bv = dv[aa]; best = aa; }
                }
                if (best < 0) break;
                used[best] = true;
                ssel[bb][cnt++] = best;
            }
            scnt[bb] = cnt;
            smc[bb]  = m;
        }
    }
    __syncthreads();

    const int cnt = scnt[b];
    const int m   = smc[b];

    float acc0[C], acc1[C];
#pragma unroll
    for (int c = 0; c < C; c++) { acc0[c] = 0.f; acc1[c] = 0.f; }

    for (int j = 0; j < cnt; j++) {
        const int a = ssel[b][j];
        const float* __restrict__ lp = auged_logits + ((size_t)(b * A + a) * C) * HW + p;
        float l0[C], l1[C];
        float mx0 = -INFINITY, mx1 = -INFINITY;
#pragma unroll
        for (int c = 0; c < C; c++) {
            float2 lv = *(const float2*)(lp + (size_t)c * HW);
            l0[c] = lv.x; l1[c] = lv.y;
            mx0 = fmaxf(mx0, lv.x); mx1 = fmaxf(mx1, lv.y);
        }
        float s0 = 0.f, s1 = 0.f;
#pragma unroll
        for (int c = 0; c < C; c++) {
            l0[c] = __expf(l0[c] - mx0); s0 += l0[c];
            l1[c] = __expf(l1[c] - mx1); s1 += l1[c];
        }
        float inv0 = 1.0f / s0, inv1 = 1.0f / s1;
#pragma unroll
        for (int c = 0; c < C; c++) {
            acc0[c] = fmaf(l0[c], inv0, acc0[c]);
            acc1[c] = fmaf(l1[c], inv1, acc1[c]);
        }
    }

    const float invc = 1.0f / (float)max(cnt, 1);

    int knn0 = 0, knn1 = 0;
    float bv0 = acc0[0], bv1 = acc1[0];
#pragma unroll
    for (int c = 1; c < C; c++) {
        if (acc0[c] > bv0) { bv0 = acc0[c]; knn0 = c; }
        if (acc1[c] > bv1) { bv1 = acc1[c]; knn1 = c; }
    }

    const bool sel = (m > 0);
    float r0 = (float)((pm0 && sel) ? knn0 : pl2.x);
    float r1 = (float)((pm1 && sel) ? knn1 : pl2.y);
    ((float2*)out)[base >> 1] = make_float2(r0, r1);

    float* __restrict__ oavg = out + (size_t)B * HW;
#pragma unroll
    for (int c = 0; c < C; c++)
        *(float2*)(oavg + ((size_t)b * C + c) * HW + p) = make_float2(acc0[c] * invc, acc1[c] * invc);
}

// ---------------- launch ----------------
extern "C" void kernel_launch(void* const* d_in, const int* in_sizes, int n_in,
                              void* d_out, int out_size) {
    const float* source_queue = (const float*)d_in[0];
    const float* tgt_feat     = (const float*)d_in[1];
    const float* tgt_logits   = (const float*)d_in[2];
    const float* auged_feat   = (const float*)d_in[3];
    const float* auged_logits = (const float*)d_in[4];
    const int*   pseudo_label = (const int*)d_in[5];
    const int*   kptr         = (n_in > 6) ? (const int*)d_in[6] : nullptr;
    float* out = (float*)d_out;

    k_dots_tt<<<NK1, 128>>>(source_queue, tgt_feat, tgt_logits);
    k_d2     <<<32 * S_D2, 256>>>(auged_feat, source_queue);
    k_final  <<<(B * HW) / 512, 256>>>(auged_logits, pseudo_label, kptr, out);
    (void)in_sizes; (void)out_size;
}